// round 14
// baseline (speedup 1.0000x reference)
#include <cuda_runtime.h>
#include <cuda_fp16.h>
#include <cstdint>

// Problem constants
#define BN   4
#define CN   128
#define HN   128
#define WN   128
#define COUT 128
#define DGN  8
#define CG   16
#define KK   9
#define HO   128
#define WO   128
#define NS   72         // (dg,k) positions == k16 slices (K = 1152)
#define PXB  64         // pixels per block
#define XP   130        // padded x slots (xs = x0+1, x0 in [-1,128])

// Scratch: pair-packed fp16 x. Slot xs holds {chans of x=xs-1 | chans of x=xs}
// for channel-quarter q. Zero-padded at x borders.
__device__ __align__(16) uint4 g_x2[BN * DGN * HN * 4 * XP];     // 34 MB
__device__ __align__(16) uint32_t g_wa[NS * 8 * 32 * 4];         // A-frag fp16x2 weights

__device__ __forceinline__ uint32_t pack_h2(float a, float b) {
    __half2 h = __floats2half2_rn(a, b);
    return *(uint32_t*)&h;
}
__device__ __forceinline__ void mma_f16(float* d, const uint32_t* a, const uint32_t* b) {
    asm volatile(
        "mma.sync.aligned.m16n8k16.row.col.f32.f16.f16.f32 "
        "{%0,%1,%2,%3}, {%4,%5,%6,%7}, {%8,%9}, {%0,%1,%2,%3};"
        : "+f"(d[0]), "+f"(d[1]), "+f"(d[2]), "+f"(d[3])
        : "r"(a[0]), "r"(a[1]), "r"(a[2]), "r"(a[3]), "r"(b[0]), "r"(b[1]));
}

// ---------------------------------------------------------------------------
// Kernel 1: x (B,C,H,W) -> pair-packed fp16 slots g_x2[bdg][y][q][xs]
// ---------------------------------------------------------------------------
__global__ void transpose_x_kernel(const float* __restrict__ x) {
    int blk = blockIdx.x;
    int y   = blk & (HN - 1);
    int bdg = blk >> 7;
    int b   = bdg >> 3;
    int dg  = bdg & 7;
    int t   = threadIdx.x;

    __shared__ float sm[CG][WN + 1];
    #pragma unroll
    for (int c = 0; c < CG; c++)
        sm[c][t] = x[((b * CN + dg * CG + c) * HN + y) * WN + t];
    __syncthreads();

    uint4* rowbase = g_x2 + (size_t)(bdg * HN + y) * (4 * XP);
    for (int xs = t; xs <= 128; xs += 128) {   // t covers 0..127; t==0 also 128
        int xlo = xs - 1, xhi = xs;
        bool vlo = (xlo >= 0), vhi = (xhi <= WN - 1);
        #pragma unroll
        for (int q = 0; q < 4; q++) {
            float l0 = vlo ? sm[q * 4 + 0][xlo] : 0.0f;
            float l1 = vlo ? sm[q * 4 + 1][xlo] : 0.0f;
            float l2 = vlo ? sm[q * 4 + 2][xlo] : 0.0f;
            float l3 = vlo ? sm[q * 4 + 3][xlo] : 0.0f;
            float h0 = vhi ? sm[q * 4 + 0][xhi] : 0.0f;
            float h1 = vhi ? sm[q * 4 + 1][xhi] : 0.0f;
            float h2 = vhi ? sm[q * 4 + 2][xhi] : 0.0f;
            float h3 = vhi ? sm[q * 4 + 3][xhi] : 0.0f;
            uint4 u;
            u.x = pack_h2(l0, l1);  u.y = pack_h2(l2, l3);
            u.z = pack_h2(h0, h1);  u.w = pack_h2(h2, h3);
            rowbase[q * XP + xs] = u;
        }
    }
}

// ---------------------------------------------------------------------------
// Kernel 2: weight -> A-fragment-ordered fp16x2 for m16n8k16 (verified)
// ---------------------------------------------------------------------------
__global__ void prep_w_kernel(const float* __restrict__ w) {
    int i = blockIdx.x * 256 + threadIdx.x;
    if (i >= NS * 8 * 32 * 4) return;
    int j    = i & 3;
    int lane = (i >> 2) & 31;
    int mt   = (i >> 7) & 7;
    int s    = i >> 10;
    int g    = lane >> 2;
    int tid  = lane & 3;
    int co   = mt * 16 + g + ((j & 1) ? 8 : 0);
    int kp   = tid * 2 + ((j >= 2) ? 8 : 0);
    int dg   = s / KK;
    int k    = s - dg * KK;
    float w0 = w[(co * CN + dg * CG + kp)     * KK + k];
    float w1 = w[(co * CN + dg * CG + kp + 1) * KK + k];
    g_wa[i] = pack_h2(w0, w1);
}

// ---------------------------------------------------------------------------
// Corner prefetch state: 2 pair-slots (y0 row, y0+1 row) + 4 folded weights
// ---------------------------------------------------------------------------
struct C4 { uint4 c[2]; float w[4]; };

__device__ __forceinline__ void issue_c4(int s, int b, int ho, int p, int q,
                                         float dy, float dx, float m, C4& C) {
    int dg = s / KK, k = s - dg * KK;
    int ky = k / 3, kx = k - ky * 3;
    float sy = dy + (float)(ho - 1 + ky);   // STRIDE=1, PAD=1, DIL=1
    float sx = dx + (float)(p - 1 + kx);
    float y0f = floorf(sy), x0f = floorf(sx);
    float ly = sy - y0f, lx = sx - x0f;
    int y0 = (int)y0f, x0 = (int)x0f;

    bool vy0 = (y0 >= 0) & (y0 < HN);
    bool vy1 = (y0 >= -1) & (y0 < HN - 1);
    bool vx0 = (x0 >= 0) & (x0 < WN);
    bool vx1 = (x0 >= -1) & (x0 < WN - 1);
    C.w[0] = (vy0 & vx0) ? (1.0f - ly) * (1.0f - lx) * m : 0.0f;
    C.w[1] = (vy0 & vx1) ? (1.0f - ly) * lx * m : 0.0f;
    C.w[2] = (vy1 & vx0) ? ly * (1.0f - lx) * m : 0.0f;
    C.w[3] = (vy1 & vx1) ? ly * lx * m : 0.0f;

    int xs  = min(max(x0, -1), WN - 1) + 1;        // 0..128
    int y0c = min(max(y0, 0), HN - 1);
    int y1c = min(max(y0 + 1, 0), HN - 1);
    int bdg = b * DGN + dg;
    const uint4* xb = g_x2 + (size_t)bdg * (HN * 4 * XP) + q * XP + xs;
    C.c[0] = __ldg(xb + (size_t)y0c * (4 * XP));
    C.c[1] = __ldg(xb + (size_t)y1c * (4 * XP));
}

__device__ __forceinline__ void combine_c4(const C4& C, float* val) {
    const __half2* h = (const __half2*)&C.c[0];
    // h[0..1]=row0 lo(x0), h[2..3]=row0 hi(x0+1), h[4..5]=row1 lo, h[6..7]=row1 hi
    float2 a0 = __half22float2(h[0]), a1 = __half22float2(h[1]);
    float2 b0 = __half22float2(h[2]), b1 = __half22float2(h[3]);
    float2 c0 = __half22float2(h[4]), c1 = __half22float2(h[5]);
    float2 e0 = __half22float2(h[6]), e1 = __half22float2(h[7]);
    val[0] = C.w[0] * a0.x + C.w[1] * b0.x + C.w[2] * c0.x + C.w[3] * e0.x;
    val[1] = C.w[0] * a0.y + C.w[1] * b0.y + C.w[2] * c0.y + C.w[3] * e0.y;
    val[2] = C.w[0] * a1.x + C.w[1] * b1.x + C.w[2] * c1.x + C.w[3] * e1.x;
    val[3] = C.w[0] * a1.y + C.w[1] * b1.y + C.w[2] * c1.y + C.w[3] * e1.y;
}

// ---------------------------------------------------------------------------
// Kernel 3: pair-sync depth-2 pipeline + fp16 m16n8k16 mma.sync.
// 64-px blocks, 2 CTAs/SM, 256 threads / 8 warps, warp tile 32(co) x 32(px).
// Pair-packed gathers: 2 LDG.128 per thread per stage (was 4 LDG.64).
// ---------------------------------------------------------------------------
__global__ __launch_bounds__(256, 2)
void dcn_main_kernel(const float* __restrict__ offset,
                     const float* __restrict__ mask,
                     const float* __restrict__ bias,
                     float*       __restrict__ out) {
    int blk = blockIdx.x;                  // ((b*HO + ho)*2 + hr)
    int hr  = blk & 1;
    int ho  = (blk >> 1) & (HO - 1);
    int b   = blk >> 8;
    int t   = threadIdx.x;
    int wid = t >> 5;
    int lane = t & 31;

    // B frags: [set][stage-in-pair][ntile(8)][lane][reg(2)] u32 -> 8KB
    __shared__ __align__(16) uint32_t bfr[2][2][8][32][2];
    // A frags: [set][stage-in-pair][mtile(8)][lane] uint4       -> 16KB
    __shared__ __align__(16) uint4 afrag[2][2][8][32];

    int m0 = (wid & 3) * 2;    // 2 mtiles per warp
    int n0 = (wid >> 2) * 4;   // 4 ntiles per warp

    // sampler mapping: 4 threads per pixel
    int q    = t & 3;          // channel quarter (c = q*4 .. q*4+3)
    int p    = t >> 2;         // local pixel (0..63)
    int pg   = hr * PXB + p;

    float d[2][4][4];
    #pragma unroll
    for (int mi = 0; mi < 2; mi++)
        #pragma unroll
        for (int ni = 0; ni < 4; ni++)
            #pragma unroll
            for (int j = 0; j < 4; j++) d[mi][ni][j] = 0.0f;

    // ---- prologue ----
    C4 CE, CO;
    uint4 aPE, aPO;
    float dyE, dxE, mE, dyO, dxO, mO;
    const int OHW = HO * WO;
    const int obase = (b * (2 * NS)) * OHW + ho * WO + pg;
    const int mbase = (b * NS) * OHW + ho * WO + pg;
    {
        float dy = __ldg(offset + obase);
        float dx = __ldg(offset + obase + OHW);
        float mm = __ldg(mask + mbase);
        issue_c4(0, b, ho, pg, q, dy, dx, mm, CE);

        dy = __ldg(offset + obase + 2 * OHW);
        dx = __ldg(offset + obase + 3 * OHW);
        mm = __ldg(mask + mbase + OHW);
        issue_c4(1, b, ho, pg, q, dy, dx, mm, CO);

        dyE = __ldg(offset + obase + 4 * OHW);
        dxE = __ldg(offset + obase + 5 * OHW);
        mE  = __ldg(mask + mbase + 2 * OHW);
        dyO = __ldg(offset + obase + 6 * OHW);
        dxO = __ldg(offset + obase + 7 * OHW);
        mO  = __ldg(mask + mbase + 3 * OHW);

        aPE = __ldg((const uint4*)g_wa + t);
        aPO = __ldg((const uint4*)(g_wa + 1024) + t);
    }

    int nt    = p >> 3;
    int lb    = (p & 7) * 4 + (q & 1) * 2;   // B-frag lane base
    int breg  = q >> 1;                      // b0 vs b1

    #pragma unroll 1
    for (int s = 0; s < NS; s += 2) {
        int set = (s >> 1) & 1;

        // ---- store prefetched A(s), A(s+1) ----
        ((uint4*)&afrag[set][0][0][0])[t] = aPE;
        ((uint4*)&afrag[set][1][0][0])[t] = aPO;

        // ---- combine corners(s), (s+1) -> B frags ----
        {
            float val[4];
            combine_c4(CE, val);
            bfr[set][0][nt][lb][breg]     = pack_h2(val[0], val[1]);
            bfr[set][0][nt][lb + 1][breg] = pack_h2(val[2], val[3]);
            combine_c4(CO, val);
            bfr[set][1][nt][lb][breg]     = pack_h2(val[0], val[1]);
            bfr[set][1][nt][lb + 1][breg] = pack_h2(val[2], val[3]);
        }

        // ---- issue corners(s+2)/(s+3); prefetch A(s+2)/(s+3); ofs depth 4 ----
        if (s + 2 < NS) {
            issue_c4(s + 2, b, ho, pg, q, dyE, dxE, mE, CE);
            issue_c4(s + 3, b, ho, pg, q, dyO, dxO, mO, CO);
            aPE = __ldg((const uint4*)(g_wa + (s + 2) * 1024) + t);
            aPO = __ldg((const uint4*)(g_wa + (s + 3) * 1024) + t);
            if (s + 4 < NS) {
                dyE = __ldg(offset + obase + (2 * (s + 4)) * OHW);
                dxE = __ldg(offset + obase + (2 * (s + 4) + 1) * OHW);
                mE  = __ldg(mask + mbase + (s + 4) * OHW);
                dyO = __ldg(offset + obase + (2 * (s + 5)) * OHW);
                dxO = __ldg(offset + obase + (2 * (s + 5) + 1) * OHW);
                mO  = __ldg(mask + mbase + (s + 5) * OHW);
            }
        }

        __syncthreads();   // frags(s, s+1) visible

        // ---- GEMM burst: 2 stages x 2 mtiles x 4 ntiles m16n8k16 ----
        #pragma unroll
        for (int st = 0; st < 2; st++) {
            uint4 af[2];
            #pragma unroll
            for (int mi = 0; mi < 2; mi++)
                af[mi] = afrag[set][st][m0 + mi][lane];
            uint2 bf[4];
            #pragma unroll
            for (int ni = 0; ni < 4; ni++)
                bf[ni] = *(const uint2*)&bfr[set][st][n0 + ni][lane][0];
            #pragma unroll
            for (int mi = 0; mi < 2; mi++)
                #pragma unroll
                for (int ni = 0; ni < 4; ni++)
                    mma_f16(d[mi][ni], (const uint32_t*)&af[mi],
                            (const uint32_t*)&bf[ni]);
        }
    }

    // ---- epilogue ----
    int g   = lane >> 2;
    int tid = lane & 3;
    #pragma unroll
    for (int mi = 0; mi < 2; mi++) {
        int co0 = (m0 + mi) * 16 + g;
        float bv0 = __ldg(bias + co0);
        float bv1 = __ldg(bias + co0 + 8);
        #pragma unroll
        for (int ni = 0; ni < 4; ni++) {
            int px = hr * PXB + (n0 + ni) * 8 + 2 * tid;
            float2 o0 = make_float2(d[mi][ni][0] + bv0, d[mi][ni][1] + bv0);
            float2 o1 = make_float2(d[mi][ni][2] + bv1, d[mi][ni][3] + bv1);
            *(float2*)(out + ((b * COUT + co0)     * HO + ho) * WO + px) = o0;
            *(float2*)(out + ((b * COUT + co0 + 8) * HO + ho) * WO + px) = o1;
        }
    }
}

// ---------------------------------------------------------------------------
// Launch
// ---------------------------------------------------------------------------
extern "C" void kernel_launch(void* const* d_in, const int* in_sizes, int n_in,
                              void* d_out, int out_size) {
    const float* x      = (const float*)d_in[0];
    const float* offset = (const float*)d_in[1];
    const float* mask   = (const float*)d_in[2];
    const float* weight = (const float*)d_in[3];
    const float* bias   = (const float*)d_in[4];
    float* out = (float*)d_out;

    transpose_x_kernel<<<BN * DGN * HN, 128>>>(x);
    prep_w_kernel<<<(NS * 8 * 32 * 4 + 255) / 256, 256>>>(weight);
    dcn_main_kernel<<<BN * HO * 2, 256>>>(offset, mask, bias, out);
}

// round 15
// speedup vs baseline: 1.0747x; 1.0747x over previous
#include <cuda_runtime.h>
#include <cuda_fp16.h>
#include <cstdint>

// Problem constants
#define BN   4
#define CN   128
#define HN   128
#define WN   128
#define COUT 128
#define DGN  8
#define CG   16
#define KK   9
#define HO   128
#define WO   128
#define NS   72         // (dg,k) positions == k16 slices (K = 1152)
#define PXB  64         // pixels per block

// Scratch
__device__ __align__(16) __half g_xt[BN * DGN * HN * WN * CG];   // x -> (B,DG,H,W,Cg) fp16
__device__ __align__(16) uint32_t g_wa[NS * 8 * 32 * 4];         // A-frag fp16x2 weights

__device__ __forceinline__ uint32_t pack_h2(float a, float b) {
    __half2 h = __floats2half2_rn(a, b);
    return *(uint32_t*)&h;
}
__device__ __forceinline__ void mma_f16(float* d, const uint32_t* a, const uint32_t* b) {
    asm volatile(
        "mma.sync.aligned.m16n8k16.row.col.f32.f16.f16.f32 "
        "{%0,%1,%2,%3}, {%4,%5,%6,%7}, {%8,%9}, {%0,%1,%2,%3};"
        : "+f"(d[0]), "+f"(d[1]), "+f"(d[2]), "+f"(d[3])
        : "r"(a[0]), "r"(a[1]), "r"(a[2]), "r"(a[3]), "r"(b[0]), "r"(b[1]));
}

// ---------------------------------------------------------------------------
// Kernel 1: transpose x (B,C,H,W) -> (B, DG, H, W, Cg) in fp16
// ---------------------------------------------------------------------------
__global__ void transpose_x_kernel(const float* __restrict__ x) {
    int blk = blockIdx.x;
    int y   = blk & (HN - 1);
    int bdg = blk >> 7;
    int b   = bdg >> 3;
    int dg  = bdg & 7;
    int t   = threadIdx.x;

    __shared__ float sm[CG][WN + 1];
    #pragma unroll
    for (int c = 0; c < CG; c++)
        sm[c][t] = x[((b * CN + dg * CG + c) * HN + y) * WN + t];
    __syncthreads();

    __half* outp = g_xt + ((bdg * HN + y) * WN + t) * CG;
    #pragma unroll
    for (int i = 0; i < 2; i++) {
        uint4 u;
        u.x = pack_h2(sm[i * 8 + 0][t], sm[i * 8 + 1][t]);
        u.y = pack_h2(sm[i * 8 + 2][t], sm[i * 8 + 3][t]);
        u.z = pack_h2(sm[i * 8 + 4][t], sm[i * 8 + 5][t]);
        u.w = pack_h2(sm[i * 8 + 6][t], sm[i * 8 + 7][t]);
        *(uint4*)(outp + i * 8) = u;
    }
}

// ---------------------------------------------------------------------------
// Kernel 2: weight -> A-fragment-ordered fp16x2 for m16n8k16 (verified)
// ---------------------------------------------------------------------------
__global__ void prep_w_kernel(const float* __restrict__ w) {
    int i = blockIdx.x * 256 + threadIdx.x;
    if (i >= NS * 8 * 32 * 4) return;
    int j    = i & 3;
    int lane = (i >> 2) & 31;
    int mt   = (i >> 7) & 7;
    int s    = i >> 10;
    int g    = lane >> 2;
    int tid  = lane & 3;
    int co   = mt * 16 + g + ((j & 1) ? 8 : 0);
    int kp   = tid * 2 + ((j >= 2) ? 8 : 0);
    int dg   = s / KK;
    int k    = s - dg * KK;
    float w0 = w[(co * CN + dg * CG + kp)     * KK + k];
    float w1 = w[(co * CN + dg * CG + kp + 1) * KK + k];
    g_wa[i] = pack_h2(w0, w1);
}

// ---------------------------------------------------------------------------
// Corner prefetch state: 4 corners x 8 fp16 channels (uint4 each) + weights
// ---------------------------------------------------------------------------
struct C8 { uint4 c[4]; float w[4]; };

__device__ __forceinline__ void issue_c8(int s, int b, int ho, int p, int h8,
                                         float dy, float dx, float m, C8& C) {
    int dg = s / KK, k = s - dg * KK;
    int ky = k / 3, kx = k - ky * 3;
    float sy = dy + (float)(ho - 1 + ky);   // STRIDE=1, PAD=1, DIL=1
    float sx = dx + (float)(p - 1 + kx);
    float y0f = floorf(sy), x0f = floorf(sx);
    float ly = sy - y0f, lx = sx - x0f;
    int y0 = (int)y0f, x0 = (int)x0f;
    float ww[4] = {(1.0f - ly) * (1.0f - lx) * m, (1.0f - ly) * lx * m,
                   ly * (1.0f - lx) * m,          ly * lx * m};
    const __half* xb = g_xt + (b * DGN + dg) * (HN * WN * CG) + h8 * 8;
    #pragma unroll
    for (int i = 0; i < 4; i++) {
        int yy = y0 + (i >> 1), xx = x0 + (i & 1);
        bool v = (yy >= 0) & (yy < HN) & (xx >= 0) & (xx < WN);
        int cy = min(max(yy, 0), HN - 1), cx = min(max(xx, 0), WN - 1);
        C.c[i] = __ldg((const uint4*)(xb + (cy * WN + cx) * CG));
        C.w[i] = v ? ww[i] : 0.0f;
    }
}

__device__ __forceinline__ void combine_c8(const C8& C, float* val) {
    #pragma unroll
    for (int j = 0; j < 8; j++) val[j] = 0.0f;
    #pragma unroll
    for (int i = 0; i < 4; i++) {
        const __half2* h = (const __half2*)&C.c[i];
        float wg = C.w[i];
        #pragma unroll
        for (int j = 0; j < 4; j++) {
            float2 f = __half22float2(h[j]);
            val[2 * j]     += wg * f.x;
            val[2 * j + 1] += wg * f.y;
        }
    }
}

// ---------------------------------------------------------------------------
// Kernel 3: pair-sync depth-2 pipeline + fp16 m16n8k16 mma.sync.
// 64-px blocks, 2 CTAs/SM, 256 threads / 8 warps, warp tile 32(co) x 32(px).
// Sampler remap: thread (p, stg, h8) handles ONE stage x 8 channels per pair
// -> index/weight math once per pair, 4x LDG.128 gathers (every byte used).
// ---------------------------------------------------------------------------
__global__ __launch_bounds__(256, 2)
void dcn_main_kernel(const float* __restrict__ offset,
                     const float* __restrict__ mask,
                     const float* __restrict__ bias,
                     float*       __restrict__ out) {
    int blk = blockIdx.x;                  // ((b*HO + ho)*2 + hr)
    int hr  = blk & 1;
    int ho  = (blk >> 1) & (HO - 1);
    int b   = blk >> 8;
    int t   = threadIdx.x;
    int wid = t >> 5;
    int lane = t & 31;

    // B frags: [set][stage-in-pair][ntile(8)][lane][reg(2)] u32 -> 8KB
    __shared__ __align__(16) uint32_t bfr[2][2][8][32][2];
    // A frags: [set][stage-in-pair][mtile(8)][lane] uint4       -> 16KB
    __shared__ __align__(16) uint4 afrag[2][2][8][32];

    int m0 = (wid & 3) * 2;    // 2 mtiles per warp
    int n0 = (wid >> 2) * 4;   // 4 ntiles per warp

    // sampler mapping: 4 threads per pixel = {stage-in-pair} x {channel half}
    int q    = t & 3;
    int stg  = q & 1;          // which stage of the pair this thread samples
    int h8   = q >> 1;         // channel half: chans h8*8 .. h8*8+7
    int p    = t >> 2;         // local pixel (0..63)
    int pg   = hr * PXB + p;

    float d[2][4][4];
    #pragma unroll
    for (int mi = 0; mi < 2; mi++)
        #pragma unroll
        for (int ni = 0; ni < 4; ni++)
            #pragma unroll
            for (int j = 0; j < 4; j++) d[mi][ni][j] = 0.0f;

    // ---- prologue ----
    C8 C;
    uint4 aPE, aPO;
    float dyN, dxN, mN;
    const int OHW = HO * WO;
    const int obase = (b * (2 * NS)) * OHW + ho * WO + pg;
    const int mbase = (b * NS) * OHW + ho * WO + pg;
    {
        int s0 = stg;                       // this thread's stage in pair 0
        float dy = __ldg(offset + obase + (2 * s0) * OHW);
        float dx = __ldg(offset + obase + (2 * s0 + 1) * OHW);
        float mm = __ldg(mask + mbase + s0 * OHW);
        issue_c8(s0, b, ho, pg, h8, dy, dx, mm, C);

        int s1 = 2 + stg;                   // this thread's stage in pair 1
        dyN = __ldg(offset + obase + (2 * s1) * OHW);
        dxN = __ldg(offset + obase + (2 * s1 + 1) * OHW);
        mN  = __ldg(mask + mbase + s1 * OHW);

        aPE = __ldg((const uint4*)g_wa + t);
        aPO = __ldg((const uint4*)(g_wa + 1024) + t);
    }

    int nt = p >> 3;
    int lb = (p & 7) * 4;

    #pragma unroll 1
    for (int s = 0; s < NS; s += 2) {
        int set = (s >> 1) & 1;

        // ---- store prefetched A(s), A(s+1) ----
        ((uint4*)&afrag[set][0][0][0])[t] = aPE;
        ((uint4*)&afrag[set][1][0][0])[t] = aPO;

        // ---- combine corners (own stage) -> B frags ----
        {
            float val[8];
            combine_c8(C, val);
            #pragma unroll
            for (int r = 0; r < 4; r++)
                bfr[set][stg][nt][lb + r][h8] = pack_h2(val[2 * r], val[2 * r + 1]);
        }

        // ---- issue corners for next pair (own stage); ofs one pair deeper ----
        if (s + 2 < NS) {
            issue_c8(s + 2 + stg, b, ho, pg, h8, dyN, dxN, mN, C);
            aPE = __ldg((const uint4*)(g_wa + (s + 2) * 1024) + t);
            aPO = __ldg((const uint4*)(g_wa + (s + 3) * 1024) + t);
            if (s + 4 < NS) {
                int sn = s + 4 + stg;
                dyN = __ldg(offset + obase + (2 * sn) * OHW);
                dxN = __ldg(offset + obase + (2 * sn + 1) * OHW);
                mN  = __ldg(mask + mbase + sn * OHW);
            }
        }

        __syncthreads();   // frags(s, s+1) visible

        // ---- GEMM burst: 2 stages x 2 mtiles x 4 ntiles m16n8k16 ----
        #pragma unroll
        for (int st = 0; st < 2; st++) {
            uint4 af[2];
            #pragma unroll
            for (int mi = 0; mi < 2; mi++)
                af[mi] = afrag[set][st][m0 + mi][lane];
            uint2 bf[4];
            #pragma unroll
            for (int ni = 0; ni < 4; ni++)
                bf[ni] = *(const uint2*)&bfr[set][st][n0 + ni][lane][0];
            #pragma unroll
            for (int mi = 0; mi < 2; mi++)
                #pragma unroll
                for (int ni = 0; ni < 4; ni++)
                    mma_f16(d[mi][ni], (const uint32_t*)&af[mi],
                            (const uint32_t*)&bf[ni]);
        }
    }

    // ---- epilogue ----
    int g   = lane >> 2;
    int tid = lane & 3;
    #pragma unroll
    for (int mi = 0; mi < 2; mi++) {
        int co0 = (m0 + mi) * 16 + g;
        float bv0 = __ldg(bias + co0);
        float bv1 = __ldg(bias + co0 + 8);
        #pragma unroll
        for (int ni = 0; ni < 4; ni++) {
            int px = hr * PXB + (n0 + ni) * 8 + 2 * tid;
            float2 o0 = make_float2(d[mi][ni][0] + bv0, d[mi][ni][1] + bv0);
            float2 o1 = make_float2(d[mi][ni][2] + bv1, d[mi][ni][3] + bv1);
            *(float2*)(out + ((b * COUT + co0)     * HO + ho) * WO + px) = o0;
            *(float2*)(out + ((b * COUT + co0 + 8) * HO + ho) * WO + px) = o1;
        }
    }
}

// ---------------------------------------------------------------------------
// Launch
// ---------------------------------------------------------------------------
extern "C" void kernel_launch(void* const* d_in, const int* in_sizes, int n_in,
                              void* d_out, int out_size) {
    const float* x      = (const float*)d_in[0];
    const float* offset = (const float*)d_in[1];
    const float* mask   = (const float*)d_in[2];
    const float* weight = (const float*)d_in[3];
    const float* bias   = (const float*)d_in[4];
    float* out = (float*)d_out;

    transpose_x_kernel<<<BN * DGN * HN, 128>>>(x);
    prep_w_kernel<<<(NS * 8 * 32 * 4 + 255) / 256, 256>>>(weight);
    dcn_main_kernel<<<BN * HO * 2, 256>>>(offset, mask, bias, out);
}

// round 16
// speedup vs baseline: 1.1016x; 1.0250x over previous
#include <cuda_runtime.h>
#include <cuda_fp16.h>
#include <cstdint>

// Problem constants
#define BN   4
#define CN   128
#define HN   128
#define WN   128
#define COUT 128
#define DGN  8
#define CG   16
#define KK   9
#define HO   128
#define WO   128
#define NS   72         // (dg,k) positions == k16 slices (K = 1152)
#define PXB  64         // pixels per block

// Scratch
__device__ __align__(16) __half g_xt[BN * DGN * HN * WN * CG];   // x -> (B,DG,H,W,Cg) fp16
__device__ __align__(16) uint32_t g_wa[NS * 8 * 32 * 4];         // A-frag fp16x2 weights

__device__ __forceinline__ uint32_t pack_h2(float a, float b) {
    __half2 h = __floats2half2_rn(a, b);
    return *(uint32_t*)&h;
}
__device__ __forceinline__ void mma_f16(float* d, const uint32_t* a, const uint32_t* b) {
    asm volatile(
        "mma.sync.aligned.m16n8k16.row.col.f32.f16.f16.f32 "
        "{%0,%1,%2,%3}, {%4,%5,%6,%7}, {%8,%9}, {%0,%1,%2,%3};"
        : "+f"(d[0]), "+f"(d[1]), "+f"(d[2]), "+f"(d[3])
        : "r"(a[0]), "r"(a[1]), "r"(a[2]), "r"(a[3]), "r"(b[0]), "r"(b[1]));
}

// ---------------------------------------------------------------------------
// Kernel 1: transpose x (B,C,H,W) -> (B, DG, H, W, Cg) in fp16
// ---------------------------------------------------------------------------
__global__ void transpose_x_kernel(const float* __restrict__ x) {
    int blk = blockIdx.x;
    int y   = blk & (HN - 1);
    int bdg = blk >> 7;
    int b   = bdg >> 3;
    int dg  = bdg & 7;
    int t   = threadIdx.x;

    __shared__ float sm[CG][WN + 1];
    #pragma unroll
    for (int c = 0; c < CG; c++)
        sm[c][t] = x[((b * CN + dg * CG + c) * HN + y) * WN + t];
    __syncthreads();

    __half* outp = g_xt + ((bdg * HN + y) * WN + t) * CG;
    #pragma unroll
    for (int i = 0; i < 2; i++) {
        uint4 u;
        u.x = pack_h2(sm[i * 8 + 0][t], sm[i * 8 + 1][t]);
        u.y = pack_h2(sm[i * 8 + 2][t], sm[i * 8 + 3][t]);
        u.z = pack_h2(sm[i * 8 + 4][t], sm[i * 8 + 5][t]);
        u.w = pack_h2(sm[i * 8 + 6][t], sm[i * 8 + 7][t]);
        *(uint4*)(outp + i * 8) = u;
    }
}

// ---------------------------------------------------------------------------
// Kernel 2: weight -> A-fragment-ordered fp16x2 for m16n8k16 (verified)
// ---------------------------------------------------------------------------
__global__ void prep_w_kernel(const float* __restrict__ w) {
    int i = blockIdx.x * 256 + threadIdx.x;
    if (i >= NS * 8 * 32 * 4) return;
    int j    = i & 3;
    int lane = (i >> 2) & 31;
    int mt   = (i >> 7) & 7;
    int s    = i >> 10;
    int g    = lane >> 2;
    int tid  = lane & 3;
    int co   = mt * 16 + g + ((j & 1) ? 8 : 0);
    int kp   = tid * 2 + ((j >= 2) ? 8 : 0);
    int dg   = s / KK;
    int k    = s - dg * KK;
    float w0 = w[(co * CN + dg * CG + kp)     * KK + k];
    float w1 = w[(co * CN + dg * CG + kp + 1) * KK + k];
    g_wa[i] = pack_h2(w0, w1);
}

// ---------------------------------------------------------------------------
// Corner prefetch state: 4 corners x 8 fp16 channels + half2 bilinear weights
// ---------------------------------------------------------------------------
struct C8 { uint4 c[4]; __half2 w[4]; };

__device__ __forceinline__ void issue_c8(int s, int b, int ho, int p, int h8,
                                         float dy, float dx, float m, C8& C) {
    int dg = s / KK, k = s - dg * KK;
    int ky = k / 3, kx = k - ky * 3;
    float sy = dy + (float)(ho - 1 + ky);   // STRIDE=1, PAD=1, DIL=1
    float sx = dx + (float)(p - 1 + kx);
    float y0f = floorf(sy), x0f = floorf(sx);
    float ly = sy - y0f, lx = sx - x0f;
    int y0 = (int)y0f, x0 = (int)x0f;
    float ww[4] = {(1.0f - ly) * (1.0f - lx) * m, (1.0f - ly) * lx * m,
                   ly * (1.0f - lx) * m,          ly * lx * m};
    const __half* xb = g_xt + (b * DGN + dg) * (HN * WN * CG) + h8 * 8;
    #pragma unroll
    for (int i = 0; i < 4; i++) {
        int yy = y0 + (i >> 1), xx = x0 + (i & 1);
        bool v = (yy >= 0) & (yy < HN) & (xx >= 0) & (xx < WN);
        int cy = min(max(yy, 0), HN - 1), cx = min(max(xx, 0), WN - 1);
        C.c[i] = __ldg((const uint4*)(xb + (cy * WN + cx) * CG));
        C.w[i] = __float2half2_rn(v ? ww[i] : 0.0f);
    }
}

// Bilinear combine in native half2: 16 HFMA2; acc[j] is the packed B-frag word.
__device__ __forceinline__ void combine_c8_h2(const C8& C, uint32_t* o) {
    __half2 acc[4];
    const __half2* h0 = (const __half2*)&C.c[0];
    #pragma unroll
    for (int j = 0; j < 4; j++) acc[j] = __hmul2(C.w[0], h0[j]);
    #pragma unroll
    for (int i = 1; i < 4; i++) {
        const __half2* h = (const __half2*)&C.c[i];
        #pragma unroll
        for (int j = 0; j < 4; j++)
            acc[j] = __hfma2(C.w[i], h[j], acc[j]);
    }
    #pragma unroll
    for (int j = 0; j < 4; j++) o[j] = *(uint32_t*)&acc[j];
}

// ---------------------------------------------------------------------------
// Kernel 3: pair-sync depth-2 pipeline + fp16 m16n8k16 mma.sync.
// 64-px blocks, 2 CTAs/SM, 256 threads / 8 warps, warp tile 32(co) x 32(px).
// Sampler: thread (p, stg, h8) = ONE stage x 8 channels; HFMA2 combine.
// ---------------------------------------------------------------------------
__global__ __launch_bounds__(256, 2)
void dcn_main_kernel(const float* __restrict__ offset,
                     const float* __restrict__ mask,
                     const float* __restrict__ bias,
                     float*       __restrict__ out) {
    int blk = blockIdx.x;                  // ((b*HO + ho)*2 + hr)
    int hr  = blk & 1;
    int ho  = (blk >> 1) & (HO - 1);
    int b   = blk >> 8;
    int t   = threadIdx.x;
    int wid = t >> 5;
    int lane = t & 31;

    // B frags: [set][stage-in-pair][ntile(8)][lane][reg(2)] u32 -> 8KB
    __shared__ __align__(16) uint32_t bfr[2][2][8][32][2];
    // A frags: [set][stage-in-pair][mtile(8)][lane] uint4       -> 16KB
    __shared__ __align__(16) uint4 afrag[2][2][8][32];

    int m0 = (wid & 3) * 2;    // 2 mtiles per warp
    int n0 = (wid >> 2) * 4;   // 4 ntiles per warp

    // sampler mapping: 4 threads per pixel = {stage-in-pair} x {channel half}
    int q    = t & 3;
    int stg  = q & 1;          // which stage of the pair this thread samples
    int h8   = q >> 1;         // channel half: chans h8*8 .. h8*8+7
    int p    = t >> 2;         // local pixel (0..63)
    int pg   = hr * PXB + p;

    float d[2][4][4];
    #pragma unroll
    for (int mi = 0; mi < 2; mi++)
        #pragma unroll
        for (int ni = 0; ni < 4; ni++)
            #pragma unroll
            for (int j = 0; j < 4; j++) d[mi][ni][j] = 0.0f;

    // ---- prologue ----
    C8 C;
    uint4 aPE, aPO;
    float dyN, dxN, mN;
    const int OHW = HO * WO;
    const int obase = (b * (2 * NS)) * OHW + ho * WO + pg;
    const int mbase = (b * NS) * OHW + ho * WO + pg;
    {
        int s0 = stg;                       // this thread's stage in pair 0
        float dy = __ldg(offset + obase + (2 * s0) * OHW);
        float dx = __ldg(offset + obase + (2 * s0 + 1) * OHW);
        float mm = __ldg(mask + mbase + s0 * OHW);
        issue_c8(s0, b, ho, pg, h8, dy, dx, mm, C);

        int s1 = 2 + stg;                   // this thread's stage in pair 1
        dyN = __ldg(offset + obase + (2 * s1) * OHW);
        dxN = __ldg(offset + obase + (2 * s1 + 1) * OHW);
        mN  = __ldg(mask + mbase + s1 * OHW);

        aPE = __ldg((const uint4*)g_wa + t);
        aPO = __ldg((const uint4*)(g_wa + 1024) + t);
    }

    int nt = p >> 3;
    int lb = (p & 7) * 4;

    #pragma unroll 1
    for (int s = 0; s < NS; s += 2) {
        int set = (s >> 1) & 1;

        // ---- store prefetched A(s), A(s+1) ----
        ((uint4*)&afrag[set][0][0][0])[t] = aPE;
        ((uint4*)&afrag[set][1][0][0])[t] = aPO;

        // ---- combine corners (own stage) -> B frags, all in half2 ----
        {
            uint32_t o[4];
            combine_c8_h2(C, o);
            #pragma unroll
            for (int r = 0; r < 4; r++)
                bfr[set][stg][nt][lb + r][h8] = o[r];
        }

        // ---- issue corners for next pair (own stage); ofs one pair deeper ----
        if (s + 2 < NS) {
            issue_c8(s + 2 + stg, b, ho, pg, h8, dyN, dxN, mN, C);
            aPE = __ldg((const uint4*)(g_wa + (s + 2) * 1024) + t);
            aPO = __ldg((const uint4*)(g_wa + (s + 3) * 1024) + t);
            if (s + 4 < NS) {
                int sn = s + 4 + stg;
                dyN = __ldg(offset + obase + (2 * sn) * OHW);
                dxN = __ldg(offset + obase + (2 * sn + 1) * OHW);
                mN  = __ldg(mask + mbase + sn * OHW);
            }
        }

        __syncthreads();   // frags(s, s+1) visible

        // ---- GEMM burst: 2 stages x 2 mtiles x 4 ntiles m16n8k16 ----
        #pragma unroll
        for (int st = 0; st < 2; st++) {
            uint4 af[2];
            #pragma unroll
            for (int mi = 0; mi < 2; mi++)
                af[mi] = afrag[set][st][m0 + mi][lane];
            uint2 bf[4];
            #pragma unroll
            for (int ni = 0; ni < 4; ni++)
                bf[ni] = *(const uint2*)&bfr[set][st][n0 + ni][lane][0];
            #pragma unroll
            for (int mi = 0; mi < 2; mi++)
                #pragma unroll
                for (int ni = 0; ni < 4; ni++)
                    mma_f16(d[mi][ni], (const uint32_t*)&af[mi],
                            (const uint32_t*)&bf[ni]);
        }
    }

    // ---- epilogue ----
    int g   = lane >> 2;
    int tid = lane & 3;
    #pragma unroll
    for (int mi = 0; mi < 2; mi++) {
        int co0 = (m0 + mi) * 16 + g;
        float bv0 = __ldg(bias + co0);
        float bv1 = __ldg(bias + co0 + 8);
        #pragma unroll
        for (int ni = 0; ni < 4; ni++) {
            int px = hr * PXB + (n0 + ni) * 8 + 2 * tid;
            float2 o0 = make_float2(d[mi][ni][0] + bv0, d[mi][ni][1] + bv0);
            float2 o1 = make_float2(d[mi][ni][2] + bv1, d[mi][ni][3] + bv1);
            *(float2*)(out + ((b * COUT + co0)     * HO + ho) * WO + px) = o0;
            *(float2*)(out + ((b * COUT + co0 + 8) * HO + ho) * WO + px) = o1;
        }
    }
}

// ---------------------------------------------------------------------------
// Launch
// ---------------------------------------------------------------------------
extern "C" void kernel_launch(void* const* d_in, const int* in_sizes, int n_in,
                              void* d_out, int out_size) {
    const float* x      = (const float*)d_in[0];
    const float* offset = (const float*)d_in[1];
    const float* mask   = (const float*)d_in[2];
    const float* weight = (const float*)d_in[3];
    const float* bias   = (const float*)d_in[4];
    float* out = (float*)d_out;

    transpose_x_kernel<<<BN * DGN * HN, 128>>>(x);
    prep_w_kernel<<<(NS * 8 * 32 * 4 + 255) / 256, 256>>>(weight);
    dcn_main_kernel<<<BN * HO * 2, 256>>>(offset, mask, bias, out);
}

// round 17
// speedup vs baseline: 1.2747x; 1.1571x over previous
#include <cuda_runtime.h>
#include <cuda_fp16.h>
#include <cstdint>

// Problem constants
#define BN   4
#define CN   128
#define HN   128
#define WN   128
#define COUT 128
#define DGN  8
#define CG   16
#define KK   9
#define HO   128
#define WO   128
#define NS   72         // (dg,k) positions == k16 slices (K = 1152)
#define PXB  64         // pixels per block

// Scratch
__device__ __align__(16) __half g_xt[BN * DGN * HN * WN * CG];   // x -> (B,DG,H,W,Cg) fp16
__device__ __align__(16) uint32_t g_wa[NS * 8 * 32 * 4];         // A-frag fp16x2 weights

__device__ __forceinline__ uint32_t pack_h2(float a, float b) {
    __half2 h = __floats2half2_rn(a, b);
    return *(uint32_t*)&h;
}
__device__ __forceinline__ uint32_t s2u(const void* p) {
    uint32_t a;
    asm("{ .reg .u64 t; cvta.to.shared.u64 t, %1; cvt.u32.u64 %0, t; }" : "=r"(a) : "l"(p));
    return a;
}
__device__ __forceinline__ void mma_f16(float* d, const uint32_t* a, const uint32_t* b) {
    asm volatile(
        "mma.sync.aligned.m16n8k16.row.col.f32.f16.f16.f32 "
        "{%0,%1,%2,%3}, {%4,%5,%6,%7}, {%8,%9}, {%0,%1,%2,%3};"
        : "+f"(d[0]), "+f"(d[1]), "+f"(d[2]), "+f"(d[3])
        : "r"(a[0]), "r"(a[1]), "r"(a[2]), "r"(a[3]), "r"(b[0]), "r"(b[1]));
}

// ---------------------------------------------------------------------------
// Kernel 1: transpose x (B,C,H,W) -> (B, DG, H, W, Cg) in fp16
// ---------------------------------------------------------------------------
__global__ void transpose_x_kernel(const float* __restrict__ x) {
    int blk = blockIdx.x;
    int y   = blk & (HN - 1);
    int bdg = blk >> 7;
    int b   = bdg >> 3;
    int dg  = bdg & 7;
    int t   = threadIdx.x;

    __shared__ float sm[CG][WN + 1];
    #pragma unroll
    for (int c = 0; c < CG; c++)
        sm[c][t] = x[((b * CN + dg * CG + c) * HN + y) * WN + t];
    __syncthreads();

    __half* outp = g_xt + ((bdg * HN + y) * WN + t) * CG;
    #pragma unroll
    for (int i = 0; i < 2; i++) {
        uint4 u;
        u.x = pack_h2(sm[i * 8 + 0][t], sm[i * 8 + 1][t]);
        u.y = pack_h2(sm[i * 8 + 2][t], sm[i * 8 + 3][t]);
        u.z = pack_h2(sm[i * 8 + 4][t], sm[i * 8 + 5][t]);
        u.w = pack_h2(sm[i * 8 + 6][t], sm[i * 8 + 7][t]);
        *(uint4*)(outp + i * 8) = u;
    }
}

// ---------------------------------------------------------------------------
// Kernel 2: weight -> A-fragment-ordered fp16x2 for m16n8k16 (verified)
// ---------------------------------------------------------------------------
__global__ void prep_w_kernel(const float* __restrict__ w) {
    int i = blockIdx.x * 256 + threadIdx.x;
    if (i >= NS * 8 * 32 * 4) return;
    int j    = i & 3;
    int lane = (i >> 2) & 31;
    int mt   = (i >> 7) & 7;
    int s    = i >> 10;
    int g    = lane >> 2;
    int tid  = lane & 3;
    int co   = mt * 16 + g + ((j & 1) ? 8 : 0);
    int kp   = tid * 2 + ((j >= 2) ? 8 : 0);
    int dg   = s / KK;
    int k    = s - dg * KK;
    float w0 = w[(co * CN + dg * CG + kp)     * KK + k];
    float w1 = w[(co * CN + dg * CG + kp + 1) * KK + k];
    g_wa[i] = pack_h2(w0, w1);
}

// ---------------------------------------------------------------------------
// Corner prefetch state: 4 corners x 8 fp16 channels + half2 bilinear weights
// ---------------------------------------------------------------------------
struct C8 { uint4 c[4]; __half2 w[4]; };

__device__ __forceinline__ void issue_c8(int dg, int k, int b, int ho, int p,
                                         int h8, float dy, float dx, float m,
                                         C8& C) {
    int ky = k / 3, kx = k - ky * 3;
    float sy = dy + (float)(ho - 1 + ky);   // STRIDE=1, PAD=1, DIL=1
    float sx = dx + (float)(p - 1 + kx);
    float y0f = floorf(sy), x0f = floorf(sx);
    float ly = sy - y0f, lx = sx - x0f;
    int y0 = (int)y0f, x0 = (int)x0f;
    float ww[4] = {(1.0f - ly) * (1.0f - lx) * m, (1.0f - ly) * lx * m,
                   ly * (1.0f - lx) * m,          ly * lx * m};
    const __half* xb = g_xt + (b * DGN + dg) * (HN * WN * CG) + h8 * 8;
    #pragma unroll
    for (int i = 0; i < 4; i++) {
        int yy = y0 + (i >> 1), xx = x0 + (i & 1);
        bool v = (yy >= 0) & (yy < HN) & (xx >= 0) & (xx < WN);
        int cy = min(max(yy, 0), HN - 1), cx = min(max(xx, 0), WN - 1);
        C.c[i] = __ldg((const uint4*)(xb + (cy * WN + cx) * CG));
        C.w[i] = __float2half2_rn(v ? ww[i] : 0.0f);
    }
}

// Bilinear combine in native half2: 16 HFMA2; acc[j] is the packed B-frag word.
__device__ __forceinline__ void combine_c8_h2(const C8& C, uint32_t* o) {
    __half2 acc[4];
    const __half2* h0 = (const __half2*)&C.c[0];
    #pragma unroll
    for (int j = 0; j < 4; j++) acc[j] = __hmul2(C.w[0], h0[j]);
    #pragma unroll
    for (int i = 1; i < 4; i++) {
        const __half2* h = (const __half2*)&C.c[i];
        #pragma unroll
        for (int j = 0; j < 4; j++)
            acc[j] = __hfma2(C.w[i], h[j], acc[j]);
    }
    #pragma unroll
    for (int j = 0; j < 4; j++) o[j] = *(uint32_t*)&acc[j];
}

// ---------------------------------------------------------------------------
// Kernel 3: quad-sync depth pipeline + fp16 m16n8k16 mma.sync.
// 64-px blocks, 2 CTAs/SM, 256 threads / 8 warps, warp tile 32(co) x 32(px).
// 4 stages per __syncthreads (18 barriers); sampler thread (p, stg, h8) does
// stages stg and stg+2 of each quad; A tiles staged with cp.async (issued
// one quad ahead); incremental (dg, k) counters (no division in the loop).
// ---------------------------------------------------------------------------
__global__ __launch_bounds__(256, 2)
void dcn_main_kernel(const float* __restrict__ offset,
                     const float* __restrict__ mask,
                     const float* __restrict__ bias,
                     float*       __restrict__ out) {
    int blk = blockIdx.x;                  // ((b*HO + ho)*2 + hr)
    int hr  = blk & 1;
    int ho  = (blk >> 1) & (HO - 1);
    int b   = blk >> 8;
    int t   = threadIdx.x;
    int wid = t >> 5;
    int lane = t & 31;

    // B frags: [set][stage-in-quad(4)][ntile(8)][lane][reg(2)] u32 -> 16KB
    __shared__ __align__(16) uint32_t bfr[2][4][8][32][2];
    // A frags: [set][stage-in-quad(4)][mtile(8)][lane] uint4       -> 32KB
    __shared__ __align__(16) uint4 afrag[2][4][8][32];

    int m0 = (wid & 3) * 2;    // 2 mtiles per warp
    int n0 = (wid >> 2) * 4;   // 4 ntiles per warp

    // sampler mapping: thread (p, stg, h8); handles quad stages stg, stg+2
    int q    = t & 3;
    int stg  = q & 1;
    int h8   = q >> 1;
    int p    = t >> 2;
    int pg   = hr * PXB + p;

    float d[2][4][4];
    #pragma unroll
    for (int mi = 0; mi < 2; mi++)
        #pragma unroll
        for (int ni = 0; ni < 4; ni++)
            #pragma unroll
            for (int j = 0; j < 4; j++) d[mi][ni][j] = 0.0f;

    const int OHW = HO * WO;
    const int obase = (b * (2 * NS)) * OHW + ho * WO + pg;
    const int mbase = (b * NS) * OHW + ho * WO + pg;

    // incremental (dg,k) counters for this thread's two stage streams
    int sA0 = stg, sB0 = stg + 2;
    int dgA = 0, kA = sA0;             // stream A: stages stg, stg+4, ...
    int dgB = 0, kB = sB0;             // stream B: stages stg+2, stg+6, ...

    // ---- prologue ----
    C8 CA, CB;
    float dyA, dxA, mA, dyB, dxB, mB;
    uint32_t a_smem = s2u(&afrag[0][0][0][0]);   // base of A frag region
    {
        float dy = __ldg(offset + obase + (2 * sA0) * OHW);
        float dx = __ldg(offset + obase + (2 * sA0 + 1) * OHW);
        float mm = __ldg(mask + mbase + sA0 * OHW);
        issue_c8(dgA, kA, b, ho, pg, h8, dy, dx, mm, CA);

        dy = __ldg(offset + obase + (2 * sB0) * OHW);
        dx = __ldg(offset + obase + (2 * sB0 + 1) * OHW);
        mm = __ldg(mask + mbase + sB0 * OHW);
        issue_c8(dgB, kB, b, ho, pg, h8, dy, dx, mm, CB);

        // offsets for quad 1 (stages +4)
        dyA = __ldg(offset + obase + (2 * (sA0 + 4)) * OHW);
        dxA = __ldg(offset + obase + (2 * (sA0 + 4) + 1) * OHW);
        mA  = __ldg(mask + mbase + (sA0 + 4) * OHW);
        dyB = __ldg(offset + obase + (2 * (sB0 + 4)) * OHW);
        dxB = __ldg(offset + obase + (2 * (sB0 + 4) + 1) * OHW);
        mB  = __ldg(mask + mbase + (sB0 + 4) * OHW);

        // cp.async A(quad 0) -> set 0 : 4 stages x 16B per thread
        #pragma unroll
        for (int st = 0; st < 4; st++) {
            uint32_t dst = a_smem + (uint32_t)(st * 4096 + t * 16);
            const void* src = (const void*)(g_wa + st * 1024 + t * 4);
            asm volatile("cp.async.cg.shared.global [%0], [%1], 16;"
                         :: "r"(dst), "l"(src) : "memory");
        }
        asm volatile("cp.async.commit_group;" ::: "memory");
    }

    int nt = p >> 3;
    int lb = (p & 7) * 4;

    #pragma unroll 1
    for (int s = 0; s < NS; s += 4) {
        int set = (s >> 2) & 1;

        // ---- combine corners (2 stages) -> B frags ----
        {
            uint32_t o[4];
            combine_c8_h2(CA, o);
            #pragma unroll
            for (int r = 0; r < 4; r++)
                bfr[set][stg][nt][lb + r][h8] = o[r];
            combine_c8_h2(CB, o);
            #pragma unroll
            for (int r = 0; r < 4; r++)
                bfr[set][stg + 2][nt][lb + r][h8] = o[r];
        }

        // ---- issue corners for next quad; refill offsets one quad deeper ----
        if (s + 4 < NS) {
            kA += 4; if (kA >= KK) { kA -= KK; dgA++; }
            kB += 4; if (kB >= KK) { kB -= KK; dgB++; }
            issue_c8(dgA, kA, b, ho, pg, h8, dyA, dxA, mA, CA);
            issue_c8(dgB, kB, b, ho, pg, h8, dyB, dxB, mB, CB);
            if (s + 8 < NS) {
                int snA = s + 8 + stg;
                int snB = snA + 2;
                dyA = __ldg(offset + obase + (2 * snA) * OHW);
                dxA = __ldg(offset + obase + (2 * snA + 1) * OHW);
                mA  = __ldg(mask + mbase + snA * OHW);
                dyB = __ldg(offset + obase + (2 * snB) * OHW);
                dxB = __ldg(offset + obase + (2 * snB + 1) * OHW);
                mB  = __ldg(mask + mbase + snB * OHW);
            }
        }

        // ---- A(quad) must have arrived ----
        asm volatile("cp.async.wait_group 0;" ::: "memory");
        __syncthreads();   // frags(quad) visible; other set free

        // ---- cp.async A(next quad) into the other set ----
        if (s + 4 < NS) {
            uint32_t dsb = a_smem + (uint32_t)((set ^ 1) * 16384 + t * 16);
            const uint32_t* srb = g_wa + (s + 4) * 1024 + t * 4;
            #pragma unroll
            for (int st = 0; st < 4; st++) {
                asm volatile("cp.async.cg.shared.global [%0], [%1], 16;"
                             :: "r"(dsb + st * 4096), "l"(srb + st * 1024)
                             : "memory");
            }
            asm volatile("cp.async.commit_group;" ::: "memory");
        }

        // ---- GEMM burst: 4 stages x 2 mtiles x 4 ntiles m16n8k16 ----
        #pragma unroll
        for (int st = 0; st < 4; st++) {
            uint4 af[2];
            #pragma unroll
            for (int mi = 0; mi < 2; mi++)
                af[mi] = afrag[set][st][m0 + mi][lane];
            uint2 bf[4];
            #pragma unroll
            for (int ni = 0; ni < 4; ni++)
                bf[ni] = *(const uint2*)&bfr[set][st][n0 + ni][lane][0];
            #pragma unroll
            for (int mi = 0; mi < 2; mi++)
                #pragma unroll
                for (int ni = 0; ni < 4; ni++)
                    mma_f16(d[mi][ni], (const uint32_t*)&af[mi],
                            (const uint32_t*)&bf[ni]);
        }
    }

    // ---- epilogue ----
    int g   = lane >> 2;
    int tid = lane & 3;
    #pragma unroll
    for (int mi = 0; mi < 2; mi++) {
        int co0 = (m0 + mi) * 16 + g;
        float bv0 = __ldg(bias + co0);
        float bv1 = __ldg(bias + co0 + 8);
        #pragma unroll
        for (int ni = 0; ni < 4; ni++) {
            int px = hr * PXB + (n0 + ni) * 8 + 2 * tid;
            float2 o0 = make_float2(d[mi][ni][0] + bv0, d[mi][ni][1] + bv0);
            float2 o1 = make_float2(d[mi][ni][2] + bv1, d[mi][ni][3] + bv1);
            *(float2*)(out + ((b * COUT + co0)     * HO + ho) * WO + px) = o0;
            *(float2*)(out + ((b * COUT + co0 + 8) * HO + ho) * WO + px) = o1;
        }
    }
}

// ---------------------------------------------------------------------------
// Launch
// ---------------------------------------------------------------------------
extern "C" void kernel_launch(void* const* d_in, const int* in_sizes, int n_in,
                              void* d_out, int out_size) {
    const float* x      = (const float*)d_in[0];
    const float* offset = (const float*)d_in[1];
    const float* mask   = (const float*)d_in[2];
    const float* weight = (const float*)d_in[3];
    const float* bias   = (const float*)d_in[4];
    float* out = (float*)d_out;

    transpose_x_kernel<<<BN * DGN * HN, 128>>>(x);
    prep_w_kernel<<<(NS * 8 * 32 * 4 + 255) / 256, 256>>>(weight);
    dcn_main_kernel<<<BN * HO * 2, 256>>>(offset, mask, bias, out);
}